// round 11
// baseline (speedup 1.0000x reference)
#include <cuda_runtime.h>
#include <cuda_bf16.h>
#include <math.h>

// ---------------- constants ----------------
#define BATCH 16
#define NPATCH 16
#define PB 256            // BATCH * NPATCH
#define PSIZE 220
#define DIM 512
#define DEPTH 6
#define HEADS 8
#define DH 64
#define MLP_ 2048
#define NC 1000
#define NTOK 17
#define ROWS 272          // BATCH * NTOK

// CNN stage dims: conv1 220->107, pool->103; conv2 103->49, pool->45; conv3 45->20, pool->16

// ---------------- scratch (device globals; no allocation) ----------------
__device__ __align__(16) float g_A[93763584];
__device__ __align__(16) float g_B[90259456];
__device__ __align__(16) float g_xproj[PB * DIM];
__device__ __align__(16) float g_x[ROWS * DIM];
__device__ __align__(16) float g_h[ROWS * DIM];
__device__ __align__(16) float g_qkv[ROWS * 3 * DIM];
__device__ __align__(16) float g_attn[ROWS * DIM];
__device__ __align__(16) float g_ff[ROWS * MLP_];
__device__ __align__(16) float g_cls[BATCH * DIM];

// ---------------- packed fp32x2 helpers (bit-exact vs scalar FFMA) ----------------
typedef unsigned long long u64_t;
__device__ __forceinline__ u64_t pack2b(float v) {
    u64_t r;
    asm("mov.b64 %0, {%1, %1};" : "=l"(r) : "f"(v));
    return r;
}
__device__ __forceinline__ void ffma2(u64_t& d, u64_t a, u64_t b) {
    asm("fma.rn.f32x2 %0, %1, %2, %0;" : "+l"(d) : "l"(a), "l"(b));
}
__device__ __forceinline__ float2 unpack2(u64_t v) {
    float2 o;
    asm("mov.b64 {%0, %1}, %2;" : "=f"(o.x), "=f"(o.y) : "l"(v));
    return o;
}

// ---------------- conv1: img patches -> [256,32,107,107], ReLU fused ----------------
// block 256 = (ly 0..15, lx 0..15); thread: 2 out rows {ty0+2ly, +1}, col tx0+lx, 32 oc
// grid (7 xtiles of 16, 4 ytiles of 32, 256 patches)
__global__ __launch_bounds__(256) void conv1_kernel(const float* __restrict__ img,
                                                    const float* __restrict__ w,
                                                    float* __restrict__ out) {
    __shared__ __align__(16) float s_in[69 * 38];   // de-interleaved: even cols [0..18], odd [19..36]
    __shared__ __align__(16) float s_w[49 * 32];    // [tap][oc]
    int p = blockIdx.z;
    int b = p >> 4, gh = (p >> 2) & 3, gw = p & 3;
    int tx0 = blockIdx.x * 16, ty0 = blockIdx.y * 32;
    int tid = threadIdx.x;
    int ly = tid >> 4, lx = tid & 15;

    for (int i = tid; i < 49 * 32; i += 256) {
        int oc = i & 31, tap = i >> 5;
        s_w[i] = w[oc * 49 + tap];
    }
    const float* ibase = img + (size_t)b * 880 * 880 + (size_t)(gh * PSIZE) * 880 + gw * PSIZE;
    int iy0 = ty0 * 2, ix0 = tx0 * 2;
    for (int i = tid; i < 69 * 37; i += 256) {
        int r = i / 37, c = i % 37;
        int y = iy0 + r, x = ix0 + c;
        float v = (y < PSIZE && x < PSIZE) ? ibase[(size_t)y * 880 + x] : 0.f;
        s_in[r * 38 + ((c & 1) ? 19 : 0) + (c >> 1)] = v;
    }
    __syncthreads();

    u64_t acc[2][16];
#pragma unroll
    for (int r = 0; r < 2; r++)
#pragma unroll
        for (int j = 0; j < 16; j++) acc[r][j] = 0ull;

#pragma unroll 1
    for (int dy = 0; dy < 7; dy++) {
#pragma unroll 1
        for (int dx = 0; dx < 7; dx++) {
            const ulonglong2* w2 = (const ulonglong2*)&s_w[(dy * 7 + dx) * 32];
            u64_t wq[16];
#pragma unroll
            for (int q = 0; q < 8; q++) {
                ulonglong2 t = w2[q];
                wq[2 * q] = t.x; wq[2 * q + 1] = t.y;
            }
            int cb = ((dx & 1) ? 19 : 0) + lx + (dx >> 1);
#pragma unroll
            for (int r = 0; r < 2; r++) {
                float iv = s_in[(4 * ly + 2 * r + dy) * 38 + cb];
                u64_t ivp = pack2b(iv);
#pragma unroll
                for (int j = 0; j < 16; j++) ffma2(acc[r][j], ivp, wq[j]);
            }
        }
    }

#pragma unroll
    for (int r = 0; r < 2; r++) {
        int oy = ty0 + 2 * ly + r, ox = tx0 + lx;
        if (oy < 107 && ox < 107) {
            size_t obase = (size_t)p * 32 * 107 * 107 + (size_t)oy * 107 + ox;
#pragma unroll
            for (int j = 0; j < 16; j++) {
                float2 v = unpack2(acc[r][j]);
                out[obase + (size_t)(2 * j) * 11449]     = fmaxf(v.x, 0.f);
                out[obase + (size_t)(2 * j + 1) * 11449] = fmaxf(v.y, 0.f);
            }
        }
    }
}

// ---------------- conv2: [256,32,103,103] -> [256,64,49,49], ReLU fused ----------------
// block 352 (343 active = ly 0..6 x lx 0..48); thread: 4 out rows {ytile*28+4ly+k}, col lx, 16 oc
// grid (2 ytiles, 4 oc-groups, 256 patches)
__global__ __launch_bounds__(352) void conv2_kernel(const float* __restrict__ in,
                                                    const float* __restrict__ w,
                                                    float* __restrict__ out) {
    __shared__ __align__(16) float s_in[61 * 104];  // de-interleaved: even [0..51], odd [52..102]
    __shared__ __align__(16) float s_w[49 * 16];    // [tap][oc_local]
    int ytile = blockIdx.x, g = blockIdx.y, p = blockIdx.z;
    int tid = threadIdx.x;
    int ly = tid / 49, lx = tid % 49;
    bool active = tid < 343;

    u64_t acc[4][8];
#pragma unroll
    for (int k = 0; k < 4; k++)
#pragma unroll
        for (int j = 0; j < 8; j++) acc[k][j] = 0ull;

    const float* inp = in + (size_t)p * 32 * 103 * 103;
    const float* wp = w + (size_t)g * 16 * 32 * 49;
    int rbase = 56 * ytile;

    for (int ic = 0; ic < 32; ic++) {
        __syncthreads();
        const float* plane = inp + (size_t)ic * 103 * 103;
        for (int i = tid; i < 61 * 103; i += 352) {
            int r = i / 103, c = i % 103;
            int gr = rbase + r; if (gr > 102) gr = 102;
            s_in[r * 104 + ((c & 1) ? 52 : 0) + (c >> 1)] = plane[gr * 103 + c];
        }
        for (int i = tid; i < 49 * 16; i += 352) {
            int tap = i >> 4, ol = i & 15;
            s_w[i] = wp[(size_t)(ol * 32 + ic) * 49 + tap];
        }
        __syncthreads();
        if (!active) continue;
#pragma unroll 1
        for (int dy = 0; dy < 7; dy++) {
#pragma unroll 1
            for (int dx = 0; dx < 7; dx++) {
                const ulonglong2* w2 = (const ulonglong2*)&s_w[(dy * 7 + dx) * 16];
                ulonglong2 t0 = w2[0], t1 = w2[1], t2 = w2[2], t3 = w2[3];
                int cb = ((dx & 1) ? 52 : 0) + lx + (dx >> 1);
#pragma unroll
                for (int k = 0; k < 4; k++) {
                    float iv = s_in[(8 * ly + 2 * k + dy) * 104 + cb];
                    u64_t ivp = pack2b(iv);
                    ffma2(acc[k][0], ivp, t0.x); ffma2(acc[k][1], ivp, t0.y);
                    ffma2(acc[k][2], ivp, t1.x); ffma2(acc[k][3], ivp, t1.y);
                    ffma2(acc[k][4], ivp, t2.x); ffma2(acc[k][5], ivp, t2.y);
                    ffma2(acc[k][6], ivp, t3.x); ffma2(acc[k][7], ivp, t3.y);
                }
            }
        }
    }
    if (active) {
#pragma unroll
        for (int k = 0; k < 4; k++) {
            int oy = ytile * 28 + 4 * ly + k;
            if (oy < 49) {
                size_t obase = ((size_t)p * 64 + g * 16) * 2401 + (size_t)oy * 49 + lx;
#pragma unroll
                for (int j = 0; j < 8; j++) {
                    float2 v = unpack2(acc[k][j]);
                    out[obase + (size_t)(2 * j) * 2401]     = fmaxf(v.x, 0.f);
                    out[obase + (size_t)(2 * j + 1) * 2401] = fmaxf(v.y, 0.f);
                }
            }
        }
    }
}

// ---------------- conv3: [256,64,45,45] -> [256,64,20,20], ReLU fused ----------------
// block 400 = (g 0..3, ry 0..4, lx 0..19); thread: 4 out rows {4ry+k}, col lx, 16 oc of group g
// grid (256 patches)
__global__ __launch_bounds__(400) void conv3_kernel(const float* __restrict__ in,
                                                    const float* __restrict__ w,
                                                    float* __restrict__ out) {
    __shared__ __align__(16) float s_in[45 * 46];   // de-interleaved: even [0..22], odd [23..44]
    __shared__ __align__(16) float s_w[49 * 64];    // [tap][oc]
    int p = blockIdx.x;
    int tid = threadIdx.x;
    int g = tid / 100, r100 = tid % 100;
    int ry = r100 / 20, lx = r100 % 20;

    u64_t acc[4][8];
#pragma unroll
    for (int k = 0; k < 4; k++)
#pragma unroll
        for (int j = 0; j < 8; j++) acc[k][j] = 0ull;

    const float* inp = in + (size_t)p * 64 * 45 * 45;

    for (int ic = 0; ic < 64; ic++) {
        __syncthreads();
        const float* plane = inp + (size_t)ic * 45 * 45;
        for (int i = tid; i < 45 * 45; i += 400) {
            int r = i / 45, c = i % 45;
            s_in[r * 46 + ((c & 1) ? 23 : 0) + (c >> 1)] = plane[i];
        }
        for (int i = tid; i < 49 * 64; i += 400) {
            int tap = i >> 6, ol = i & 63;
            s_w[i] = w[(size_t)(ol * 64 + ic) * 49 + tap];
        }
        __syncthreads();
#pragma unroll 1
        for (int dy = 0; dy < 7; dy++) {
#pragma unroll 1
            for (int dx = 0; dx < 7; dx++) {
                const ulonglong2* w2 = (const ulonglong2*)&s_w[(dy * 7 + dx) * 64 + g * 16];
                ulonglong2 t0 = w2[0], t1 = w2[1], t2 = w2[2], t3 = w2[3];
                int cb = ((dx & 1) ? 23 : 0) + lx + (dx >> 1);
#pragma unroll
                for (int k = 0; k < 4; k++) {
                    float iv = s_in[(8 * ry + 2 * k + dy) * 46 + cb];
                    u64_t ivp = pack2b(iv);
                    ffma2(acc[k][0], ivp, t0.x); ffma2(acc[k][1], ivp, t0.y);
                    ffma2(acc[k][2], ivp, t1.x); ffma2(acc[k][3], ivp, t1.y);
                    ffma2(acc[k][4], ivp, t2.x); ffma2(acc[k][5], ivp, t2.y);
                    ffma2(acc[k][6], ivp, t3.x); ffma2(acc[k][7], ivp, t3.y);
                }
            }
        }
    }
#pragma unroll
    for (int k = 0; k < 4; k++) {
        int oy = 4 * ry + k;
        size_t obase = ((size_t)p * 64 + g * 16) * 400 + (size_t)oy * 20 + lx;
#pragma unroll
        for (int j = 0; j < 8; j++) {
            float2 v = unpack2(acc[k][j]);
            out[obase + (size_t)(2 * j) * 400]     = fmaxf(v.x, 0.f);
            out[obase + (size_t)(2 * j + 1) * 400] = fmaxf(v.y, 0.f);
        }
    }
}

// ---------------- separable maxpool 7x7 s1 p1 ----------------
__global__ void poolH_kernel(const float* __restrict__ in, float* __restrict__ out,
                             int planes, int H, int W) {
    int Wo = W - 4;
    long total = (long)planes * H * Wo;
    long idx = (long)blockIdx.x * 256 + threadIdx.x;
    if (idx >= total) return;
    int ox = (int)(idx % Wo);
    long rest = idx / Wo;
    int y = (int)(rest % H);
    long pl = rest / H;
    const float* row = in + ((long)pl * H + y) * W;
    float m = -1e30f;
#pragma unroll
    for (int k = 0; k < 7; k++) {
        int x = ox - 1 + k;
        if (x >= 0 && x < W) m = fmaxf(m, row[x]);
    }
    out[idx] = m;
}

__global__ void poolV_kernel(const float* __restrict__ in, float* __restrict__ out,
                             int planes, int H, int W) {
    int Ho = H - 4;
    long total = (long)planes * Ho * W;
    long idx = (long)blockIdx.x * 256 + threadIdx.x;
    if (idx >= total) return;
    int x = (int)(idx % W);
    long rest = idx / W;
    int oy = (int)(rest % Ho);
    long pl = rest / Ho;
    const float* base = in + (long)pl * H * W;
    float m = -1e30f;
#pragma unroll
    for (int k = 0; k < 7; k++) {
        int r = oy - 1 + k;
        if (r >= 0 && r < H) m = fmaxf(m, base[(long)r * W + x]);
    }
    out[idx] = m;
}

// ---------------- generic fp32 GEMM (+epilogue) ----------------
__device__ __forceinline__ float gelu_exact(float v) {
    return 0.5f * v * (1.0f + erff(v * 0.70710678118654752440f));
}

__global__ void gemm_kernel(const float* __restrict__ A, const float* __restrict__ W,
                            const float* __restrict__ bias, const float* resid,
                            float* C, int M, int N, int K, int mode) {
    __shared__ __align__(16) float As[16][65];
    __shared__ __align__(16) float Ws[16][64];
    int tid = threadIdx.x;
    int tx = tid & 15, ty = tid >> 4;
    int n0 = blockIdx.x * 64, m0 = blockIdx.y * 64;
    int kpb = K / gridDim.z;
    int kbeg = blockIdx.z * kpb, kend = kbeg + kpb;

    float acc[4][4];
#pragma unroll
    for (int i = 0; i < 4; i++)
#pragma unroll
        for (int j = 0; j < 4; j++) acc[i][j] = 0.f;

    int a_m = tid >> 2, a_k4 = (tid & 3) * 4;
    int w_k = tid >> 4, w_n4 = (tid & 15) * 4;

    for (int k0 = kbeg; k0 < kend; k0 += 16) {
        float4 av = make_float4(0.f, 0.f, 0.f, 0.f);
        if (m0 + a_m < M)
            av = *(const float4*)(A + (size_t)(m0 + a_m) * K + k0 + a_k4);
        As[a_k4 + 0][a_m] = av.x;
        As[a_k4 + 1][a_m] = av.y;
        As[a_k4 + 2][a_m] = av.z;
        As[a_k4 + 3][a_m] = av.w;
        *(float4*)&Ws[w_k][w_n4] = *(const float4*)(W + (size_t)(k0 + w_k) * N + n0 + w_n4);
        __syncthreads();
#pragma unroll
        for (int kk = 0; kk < 16; kk++) {
            float4 bv = *(const float4*)&Ws[kk][tx * 4];
            float a0 = As[kk][ty * 4 + 0];
            float a1 = As[kk][ty * 4 + 1];
            float a2 = As[kk][ty * 4 + 2];
            float a3 = As[kk][ty * 4 + 3];
            acc[0][0] += a0 * bv.x; acc[0][1] += a0 * bv.y; acc[0][2] += a0 * bv.z; acc[0][3] += a0 * bv.w;
            acc[1][0] += a1 * bv.x; acc[1][1] += a1 * bv.y; acc[1][2] += a1 * bv.z; acc[1][3] += a1 * bv.w;
            acc[2][0] += a2 * bv.x; acc[2][1] += a2 * bv.y; acc[2][2] += a2 * bv.z; acc[2][3] += a2 * bv.w;
            acc[3][0] += a3 * bv.x; acc[3][1] += a3 * bv.y; acc[3][2] += a3 * bv.z; acc[3][3] += a3 * bv.w;
        }
        __syncthreads();
    }

#pragma unroll
    for (int i = 0; i < 4; i++) {
        int m = m0 + ty * 4 + i;
        if (m >= M) continue;
#pragma unroll
        for (int j = 0; j < 4; j++) {
            int n = n0 + tx * 4 + j;
            float v = acc[i][j];
            if (mode == 3) {
                atomicAdd(&C[(size_t)m * N + n], v);
            } else {
                if (bias) v += bias[n];
                if (mode == 2) v = gelu_exact(v);
                if (mode == 1) v += resid[(size_t)m * N + n];
                C[(size_t)m * N + n] = v;
            }
        }
    }
}

// ---------------- layernorm (width 512) ----------------
__global__ void ln_kernel(const float* __restrict__ in, int row_stride,
                          const float* __restrict__ g, const float* __restrict__ b,
                          float* __restrict__ out) {
    int r = blockIdx.x;
    const float* x = in + (size_t)r * row_stride;
    int tid = threadIdx.x;  // 128
    float4 v = *(const float4*)(x + tid * 4);
    float s = v.x + v.y + v.z + v.w;
    float ss = v.x * v.x + v.y * v.y + v.z * v.z + v.w * v.w;
    __shared__ float rs[4], rss[4];
#pragma unroll
    for (int o = 16; o > 0; o >>= 1) {
        s += __shfl_down_sync(0xffffffffu, s, o);
        ss += __shfl_down_sync(0xffffffffu, ss, o);
    }
    int lane = tid & 31, wp = tid >> 5;
    if (lane == 0) { rs[wp] = s; rss[wp] = ss; }
    __syncthreads();
    float S = rs[0] + rs[1] + rs[2] + rs[3];
    float SS = rss[0] + rss[1] + rss[2] + rss[3];
    float mean = S * (1.f / 512.f);
    float var = SS * (1.f / 512.f) - mean * mean;
    float inv = rsqrtf(var + 1e-5f);
    float4 gv = *(const float4*)(g + tid * 4);
    float4 bv = *(const float4*)(b + tid * 4);
    float4 o;
    o.x = (v.x - mean) * inv * gv.x + bv.x;
    o.y = (v.y - mean) * inv * gv.y + bv.y;
    o.z = (v.z - mean) * inv * gv.z + bv.z;
    o.w = (v.w - mean) * inv * gv.w + bv.w;
    *(float4*)(out + (size_t)r * 512 + tid * 4) = o;
}

// ---------------- attention: per (head, batch) block ----------------
__global__ void attn_kernel(const float* __restrict__ qkv, float* __restrict__ attnout) {
    int h = blockIdx.x, b = blockIdx.y;
    __shared__ float sq[17][65], sk[17][65], sv[17][65], sp[17][18];
    int tid = threadIdx.x;  // 128
    for (int idx = tid; idx < 17 * 64; idx += 128) {
        int n = idx >> 6, d = idx & 63;
        const float* row = qkv + (size_t)(b * 17 + n) * 1536 + h * 64 + d;
        sq[n][d] = row[0];
        sk[n][d] = row[512];
        sv[n][d] = row[1024];
    }
    __syncthreads();
    for (int idx = tid; idx < 289; idx += 128) {
        int qi = idx / 17, ki = idx % 17;
        float s = 0.f;
#pragma unroll
        for (int d = 0; d < 64; d++) s += sq[qi][d] * sk[ki][d];
        sp[qi][ki] = s * 0.125f;
    }
    __syncthreads();
    if (tid < 17) {
        float m = -1e30f;
        for (int k = 0; k < 17; k++) m = fmaxf(m, sp[tid][k]);
        float sum = 0.f;
        for (int k = 0; k < 17; k++) { float e = expf(sp[tid][k] - m); sp[tid][k] = e; sum += e; }
        float inv = 1.f / sum;
        for (int k = 0; k < 17; k++) sp[tid][k] *= inv;
    }
    __syncthreads();
    for (int idx = tid; idx < 17 * 64; idx += 128) {
        int n = idx >> 6, d = idx & 63;
        float o = 0.f;
#pragma unroll
        for (int k = 0; k < 17; k++) o += sp[n][k] * sv[k][d];
        attnout[(size_t)(b * 17 + n) * 512 + h * 64 + d] = o;
    }
}

// ---------------- assemble tokens ----------------
__global__ void assemble_kernel(const float* __restrict__ xproj, const float* __restrict__ flat_b,
                                const float* __restrict__ cls_token, const float* __restrict__ pos_emb,
                                float* __restrict__ x) {
    int idx = blockIdx.x * 256 + threadIdx.x;
    if (idx >= BATCH * NTOK * DIM) return;
    int d = idx & 511;
    int r = (idx >> 9) % NTOK;
    int b = idx / (NTOK * DIM);
    float v;
    if (r == 0)
        v = cls_token[d] + pos_emb[d];
    else
        v = xproj[(size_t)(b * NPATCH + (r - 1)) * DIM + d] + flat_b[d] + pos_emb[r * DIM + d];
    x[idx] = v;
}

__global__ void zero_kernel(float* p, int n) {
    int i = blockIdx.x * 256 + threadIdx.x;
    if (i < n) p[i] = 0.f;
}

// ---------------- head ----------------
__global__ void head_kernel(const float* __restrict__ cls, const float* __restrict__ hw,
                            const float* __restrict__ hb, float* __restrict__ out) {
    int b = blockIdx.x;
    __shared__ float s[512];
    int tid = threadIdx.x;  // 256
    s[tid] = cls[(size_t)b * 512 + tid];
    s[tid + 256] = cls[(size_t)b * 512 + tid + 256];
    __syncthreads();
    for (int c = tid; c < NC; c += 256) {
        float acc = hb[c];
        for (int k = 0; k < 512; k++) acc += s[k] * hw[(size_t)k * NC + c];
        out[(size_t)b * NC + c] = acc;
    }
}

// ---------------- launch ----------------
static inline int cdiv_l(long a, int b) { return (int)((a + b - 1) / b); }

extern "C" void kernel_launch(void* const* d_in, const int* in_sizes, int n_in,
                              void* d_out, int out_size) {
    const float* img      = (const float*)d_in[0];
    const float* conv1_w  = (const float*)d_in[1];
    const float* conv2_w  = (const float*)d_in[2];
    const float* conv3_w  = (const float*)d_in[3];
    const float* flat_w   = (const float*)d_in[4];
    const float* flat_b   = (const float*)d_in[5];
    const float* cls_tok  = (const float*)d_in[6];
    const float* pos_emb  = (const float*)d_in[7];
    const float* ln1_g    = (const float*)d_in[8];
    const float* ln1_b    = (const float*)d_in[9];
    const float* qkv_w    = (const float*)d_in[10];
    const float* out_w    = (const float*)d_in[11];
    const float* out_b    = (const float*)d_in[12];
    const float* ln2_g    = (const float*)d_in[13];
    const float* ln2_b    = (const float*)d_in[14];
    const float* ff1_w    = (const float*)d_in[15];
    const float* ff1_b    = (const float*)d_in[16];
    const float* ff2_w    = (const float*)d_in[17];
    const float* ff2_b    = (const float*)d_in[18];
    const float* hln_g    = (const float*)d_in[19];
    const float* hln_b    = (const float*)d_in[20];
    const float* head_w   = (const float*)d_in[21];
    const float* head_b   = (const float*)d_in[22];
    float* outp = (float*)d_out;

    float *A, *Bb, *xproj, *x, *h, *qkv, *attn, *ff, *cls;
    cudaGetSymbolAddress((void**)&A, g_A);
    cudaGetSymbolAddress((void**)&Bb, g_B);
    cudaGetSymbolAddress((void**)&xproj, g_xproj);
    cudaGetSymbolAddress((void**)&x, g_x);
    cudaGetSymbolAddress((void**)&h, g_h);
    cudaGetSymbolAddress((void**)&qkv, g_qkv);
    cudaGetSymbolAddress((void**)&attn, g_attn);
    cudaGetSymbolAddress((void**)&ff, g_ff);
    cudaGetSymbolAddress((void**)&cls, g_cls);

    // --- CNN stage 1 ---
    conv1_kernel<<<dim3(7, 4, PB), 256>>>(img, conv1_w, A);
    {
        long t = (long)PB * 32 * 107 * 103;
        poolH_kernel<<<cdiv_l(t, 256), 256>>>(A, Bb, PB * 32, 107, 107);
        t = (long)PB * 32 * 103 * 103;
        poolV_kernel<<<cdiv_l(t, 256), 256>>>(Bb, A, PB * 32, 107, 103);
    }
    // --- CNN stage 2 ---
    conv2_kernel<<<dim3(2, 4, PB), 352>>>(A, conv2_w, Bb);
    {
        long t = (long)PB * 64 * 49 * 45;
        poolH_kernel<<<cdiv_l(t, 256), 256>>>(Bb, A, PB * 64, 49, 49);
        t = (long)PB * 64 * 45 * 45;
        poolV_kernel<<<cdiv_l(t, 256), 256>>>(A, Bb, PB * 64, 49, 45);
    }
    // --- CNN stage 3 ---
    conv3_kernel<<<PB, 400>>>(Bb, conv3_w, A);
    {
        long t = (long)PB * 64 * 20 * 16;
        poolH_kernel<<<cdiv_l(t, 256), 256>>>(A, Bb, PB * 64, 20, 20);
        t = (long)PB * 64 * 16 * 16;
        poolV_kernel<<<cdiv_l(t, 256), 256>>>(Bb, A, PB * 64, 20, 16);
    }
    // feat = A : [256, 16384]

    // --- flat projection (split-K=8, atomic) ---
    zero_kernel<<<cdiv_l(PB * DIM, 256), 256>>>(xproj, PB * DIM);
    gemm_kernel<<<dim3(DIM / 64, PB / 64, 8), 256>>>(A, flat_w, nullptr, nullptr, xproj,
                                                     PB, DIM, 16384, 3);
    assemble_kernel<<<cdiv_l(BATCH * NTOK * DIM, 256), 256>>>(xproj, flat_b, cls_tok, pos_emb, x);

    // --- transformer ---
    for (int l = 0; l < DEPTH; l++) {
        const float* qw = qkv_w + (size_t)l * DIM * 3 * DIM;
        const float* ow = out_w + (size_t)l * DIM * DIM;
        const float* ob = out_b + (size_t)l * DIM;
        const float* w1 = ff1_w + (size_t)l * DIM * MLP_;
        const float* b1 = ff1_b + (size_t)l * MLP_;
        const float* w2 = ff2_w + (size_t)l * MLP_ * DIM;
        const float* b2 = ff2_b + (size_t)l * DIM;

        ln_kernel<<<ROWS, 128>>>(x, DIM, ln1_g + l * DIM, ln1_b + l * DIM, h);
        gemm_kernel<<<dim3(1536 / 64, 5, 1), 256>>>(h, qw, nullptr, nullptr, qkv,
                                                    ROWS, 1536, DIM, 0);
        attn_kernel<<<dim3(HEADS, BATCH), 128>>>(qkv, attn);
        gemm_kernel<<<dim3(DIM / 64, 5, 1), 256>>>(attn, ow, ob, x, x,
                                                   ROWS, DIM, DIM, 1);
        ln_kernel<<<ROWS, 128>>>(x, DIM, ln2_g + l * DIM, ln2_b + l * DIM, h);
        gemm_kernel<<<dim3(MLP_ / 64, 5, 1), 256>>>(h, w1, b1, nullptr, ff,
                                                    ROWS, MLP_, DIM, 2);
        gemm_kernel<<<dim3(DIM / 64, 5, 1), 256>>>(ff, w2, b2, x, x,
                                                   ROWS, DIM, MLP_, 1);
    }

    // --- head ---
    ln_kernel<<<BATCH, 128>>>(x, NTOK * DIM, hln_g, hln_b, cls);
    head_kernel<<<BATCH, 256>>>(cls, head_w, head_b, outp);
}

// round 12
// speedup vs baseline: 1.2562x; 1.2562x over previous
#include <cuda_runtime.h>
#include <cuda_bf16.h>
#include <math.h>

// ---------------- constants ----------------
#define BATCH 16
#define NPATCH 16
#define PB 256            // BATCH * NPATCH
#define PSIZE 220
#define DIM 512
#define DEPTH 6
#define HEADS 8
#define DH 64
#define MLP_ 2048
#define NC 1000
#define NTOK 17
#define ROWS 272          // BATCH * NTOK

// CNN stage dims: conv1 220->107, pool->103; conv2 103->49, pool->45; conv3 45->20, pool->16

// ---------------- scratch (device globals; no allocation) ----------------
__device__ __align__(16) float g_A[93763584];
__device__ __align__(16) float g_B[90259456];
__device__ __align__(16) float g_xproj[PB * DIM];
__device__ __align__(16) float g_x[ROWS * DIM];
__device__ __align__(16) float g_h[ROWS * DIM];
__device__ __align__(16) float g_qkv[ROWS * 3 * DIM];
__device__ __align__(16) float g_attn[ROWS * DIM];
__device__ __align__(16) float g_ff[ROWS * MLP_];
__device__ __align__(16) float g_cls[BATCH * DIM];

// ---------------- packed fp32x2 helpers (bit-exact vs scalar FFMA) ----------------
typedef unsigned long long u64_t;
__device__ __forceinline__ u64_t pack2b(float v) {
    u64_t r;
    asm("mov.b64 %0, {%1, %1};" : "=l"(r) : "f"(v));
    return r;
}
__device__ __forceinline__ void ffma2(u64_t& d, u64_t a, u64_t b) {
    asm("fma.rn.f32x2 %0, %1, %2, %0;" : "+l"(d) : "l"(a), "l"(b));
}
__device__ __forceinline__ float2 unpack2(u64_t v) {
    float2 o;
    asm("mov.b64 {%0, %1}, %2;" : "=f"(o.x), "=f"(o.y) : "l"(v));
    return o;
}

// ---------------- conv1: img patches -> [256,32,107,107], ReLU fused ----------------
// grid (7 xtiles, 4 ytiles * 2 ocg, 256 patches), block 256 = (ly 0..15, lx 0..15)
// thread: 2 out rows, 1 col, 16 oc  -> acc[2][8] u64
__global__ __launch_bounds__(256, 3) void conv1_kernel(const float* __restrict__ img,
                                                       const float* __restrict__ w,
                                                       float* __restrict__ out) {
    __shared__ __align__(16) float s_in[69 * 38];   // de-interleaved: even cols [0..18], odd [19..36]
    __shared__ __align__(16) float s_w[49 * 16];    // [tap][oc_local]
    int p = blockIdx.z;
    int b = p >> 4, gh = (p >> 2) & 3, gw = p & 3;
    int ytile = blockIdx.y & 3, ocg = blockIdx.y >> 2;
    int tx0 = blockIdx.x * 16, ty0 = ytile * 32;
    int tid = threadIdx.x;
    int ly = tid >> 4, lx = tid & 15;

    for (int i = tid; i < 49 * 16; i += 256) {
        int ol = i & 15, tap = i >> 4;
        s_w[i] = w[(ocg * 16 + ol) * 49 + tap];
    }
    const float* ibase = img + (size_t)b * 880 * 880 + (size_t)(gh * PSIZE) * 880 + gw * PSIZE;
    int iy0 = ty0 * 2, ix0 = tx0 * 2;
    for (int i = tid; i < 69 * 37; i += 256) {
        int r = i / 37, c = i % 37;
        int y = iy0 + r, x = ix0 + c;
        float v = (y < PSIZE && x < PSIZE) ? ibase[(size_t)y * 880 + x] : 0.f;
        s_in[r * 38 + ((c & 1) ? 19 : 0) + (c >> 1)] = v;
    }
    __syncthreads();

    u64_t acc[2][8];
#pragma unroll
    for (int r = 0; r < 2; r++)
#pragma unroll
        for (int j = 0; j < 8; j++) acc[r][j] = 0ull;

#pragma unroll 1
    for (int dy = 0; dy < 7; dy++) {
#pragma unroll
        for (int dx = 0; dx < 7; dx++) {
            const ulonglong2* w2 = (const ulonglong2*)&s_w[(dy * 7 + dx) * 16];
            ulonglong2 ta = w2[0], tb = w2[1], tc = w2[2], td = w2[3];
            int cb = ((dx & 1) ? 19 : 0) + lx + (dx >> 1);
#pragma unroll
            for (int r = 0; r < 2; r++) {
                float iv = s_in[(4 * ly + 2 * r + dy) * 38 + cb];
                u64_t ivp = pack2b(iv);
                ffma2(acc[r][0], ivp, ta.x); ffma2(acc[r][1], ivp, ta.y);
                ffma2(acc[r][2], ivp, tb.x); ffma2(acc[r][3], ivp, tb.y);
                ffma2(acc[r][4], ivp, tc.x); ffma2(acc[r][5], ivp, tc.y);
                ffma2(acc[r][6], ivp, td.x); ffma2(acc[r][7], ivp, td.y);
            }
        }
    }

#pragma unroll
    for (int r = 0; r < 2; r++) {
        int oy = ty0 + 2 * ly + r, ox = tx0 + lx;
        if (oy < 107 && ox < 107) {
            size_t obase = ((size_t)p * 32 + ocg * 16) * 11449 + (size_t)oy * 107 + ox;
#pragma unroll
            for (int j = 0; j < 8; j++) {
                float2 v = unpack2(acc[r][j]);
                out[obase + (size_t)(2 * j) * 11449]     = fmaxf(v.x, 0.f);
                out[obase + (size_t)(2 * j + 1) * 11449] = fmaxf(v.y, 0.f);
            }
        }
    }
}

// ---------------- conv2: [256,32,103,103] -> [256,64,49,49], ReLU fused ----------------
// grid (2 ytiles, 8 ocg of 8, 256 patches), block 352 (343 active = ly 0..6 x lx 0..48)
// thread: 4 out rows, 1 col, 8 oc -> acc[4][4] u64
__global__ __launch_bounds__(352, 3) void conv2_kernel(const float* __restrict__ in,
                                                       const float* __restrict__ w,
                                                       float* __restrict__ out) {
    __shared__ __align__(16) float s_in[61 * 104];  // de-interleaved: even [0..51], odd [52..102]
    __shared__ __align__(16) float s_w[49 * 8];     // [tap][oc_local]
    int ytile = blockIdx.x, g = blockIdx.y, p = blockIdx.z;
    int tid = threadIdx.x;
    int ly = tid / 49, lx = tid % 49;
    bool active = tid < 343;

    u64_t acc[4][4];
#pragma unroll
    for (int k = 0; k < 4; k++)
#pragma unroll
        for (int j = 0; j < 4; j++) acc[k][j] = 0ull;

    const float* inp = in + (size_t)p * 32 * 103 * 103;
    const float* wp = w + (size_t)g * 8 * 32 * 49;
    int rbase = 56 * ytile;

    for (int ic = 0; ic < 32; ic++) {
        __syncthreads();
        const float* plane = inp + (size_t)ic * 103 * 103;
        for (int i = tid; i < 61 * 103; i += 352) {
            int r = i / 103, c = i % 103;
            int gr = rbase + r; if (gr > 102) gr = 102;
            s_in[r * 104 + ((c & 1) ? 52 : 0) + (c >> 1)] = plane[gr * 103 + c];
        }
        for (int i = tid; i < 49 * 8; i += 352) {
            int tap = i >> 3, ol = i & 7;
            s_w[i] = wp[(size_t)(ol * 32 + ic) * 49 + tap];
        }
        __syncthreads();
        if (!active) continue;
#pragma unroll 1
        for (int dy = 0; dy < 7; dy++) {
#pragma unroll
            for (int dx = 0; dx < 7; dx++) {
                const ulonglong2* w2 = (const ulonglong2*)&s_w[(dy * 7 + dx) * 8];
                ulonglong2 t0 = w2[0], t1 = w2[1];
                int cb = ((dx & 1) ? 52 : 0) + lx + (dx >> 1);
#pragma unroll
                for (int k = 0; k < 4; k++) {
                    float iv = s_in[(8 * ly + 2 * k + dy) * 104 + cb];
                    u64_t ivp = pack2b(iv);
                    ffma2(acc[k][0], ivp, t0.x); ffma2(acc[k][1], ivp, t0.y);
                    ffma2(acc[k][2], ivp, t1.x); ffma2(acc[k][3], ivp, t1.y);
                }
            }
        }
    }
    if (active) {
#pragma unroll
        for (int k = 0; k < 4; k++) {
            int oy = ytile * 28 + 4 * ly + k;
            if (oy < 49) {
                size_t obase = ((size_t)p * 64 + g * 8) * 2401 + (size_t)oy * 49 + lx;
#pragma unroll
                for (int j = 0; j < 4; j++) {
                    float2 v = unpack2(acc[k][j]);
                    out[obase + (size_t)(2 * j) * 2401]     = fmaxf(v.x, 0.f);
                    out[obase + (size_t)(2 * j + 1) * 2401] = fmaxf(v.y, 0.f);
                }
            }
        }
    }
}

// ---------------- conv3: [256,64,45,45] -> [256,64,20,20], ReLU fused ----------------
// grid (2 ytiles * 2 ocg of 32, 256 patches), block 400 = (sub 0..3 of 8 oc, ry 0..4, lx 0..19)
// thread: 2 out rows {ytile*10+2ry, +1}, 1 col, 8 oc -> acc[2][4] u64
__global__ __launch_bounds__(400, 3) void conv3_kernel(const float* __restrict__ in,
                                                       const float* __restrict__ w,
                                                       float* __restrict__ out) {
    __shared__ __align__(16) float s_in[45 * 46];   // de-interleaved: even [0..22], odd [23..44]
    __shared__ __align__(16) float s_w[49 * 32];    // [tap][oc_local]
    int ytile = blockIdx.x & 1, ocg = blockIdx.x >> 1;
    int p = blockIdx.y;
    int tid = threadIdx.x;
    int sub = tid / 100, r100 = tid % 100;
    int ry = r100 / 20, lx = r100 % 20;

    u64_t acc[2][4];
#pragma unroll
    for (int k = 0; k < 2; k++)
#pragma unroll
        for (int j = 0; j < 4; j++) acc[k][j] = 0ull;

    const float* inp = in + (size_t)p * 64 * 45 * 45;

    for (int ic = 0; ic < 64; ic++) {
        __syncthreads();
        const float* plane = inp + (size_t)ic * 45 * 45;
        for (int i = tid; i < 45 * 45; i += 400) {
            int r = i / 45, c = i % 45;
            s_in[r * 46 + ((c & 1) ? 23 : 0) + (c >> 1)] = plane[i];
        }
        for (int i = tid; i < 49 * 32; i += 400) {
            int tap = i >> 5, ol = i & 31;
            s_w[i] = w[(size_t)((ocg * 32 + ol) * 64 + ic) * 49 + tap];
        }
        __syncthreads();
#pragma unroll 1
        for (int dy = 0; dy < 7; dy++) {
#pragma unroll
            for (int dx = 0; dx < 7; dx++) {
                const ulonglong2* w2 = (const ulonglong2*)&s_w[(dy * 7 + dx) * 32 + sub * 8];
                ulonglong2 t0 = w2[0], t1 = w2[1];
                int cb = ((dx & 1) ? 23 : 0) + lx + (dx >> 1);
#pragma unroll
                for (int k = 0; k < 2; k++) {
                    float iv = s_in[(20 * ytile + 4 * ry + 2 * k + dy) * 46 + cb];
                    u64_t ivp = pack2b(iv);
                    ffma2(acc[k][0], ivp, t0.x); ffma2(acc[k][1], ivp, t0.y);
                    ffma2(acc[k][2], ivp, t1.x); ffma2(acc[k][3], ivp, t1.y);
                }
            }
        }
    }
#pragma unroll
    for (int k = 0; k < 2; k++) {
        int oy = ytile * 10 + 2 * ry + k;
        size_t obase = ((size_t)p * 64 + ocg * 32 + sub * 8) * 400 + (size_t)oy * 20 + lx;
#pragma unroll
        for (int j = 0; j < 4; j++) {
            float2 v = unpack2(acc[k][j]);
            out[obase + (size_t)(2 * j) * 400]     = fmaxf(v.x, 0.f);
            out[obase + (size_t)(2 * j + 1) * 400] = fmaxf(v.y, 0.f);
        }
    }
}

// ---------------- separable maxpool 7x7 s1 p1 ----------------
__global__ void poolH_kernel(const float* __restrict__ in, float* __restrict__ out,
                             int planes, int H, int W) {
    int Wo = W - 4;
    long total = (long)planes * H * Wo;
    long idx = (long)blockIdx.x * 256 + threadIdx.x;
    if (idx >= total) return;
    int ox = (int)(idx % Wo);
    long rest = idx / Wo;
    int y = (int)(rest % H);
    long pl = rest / H;
    const float* row = in + ((long)pl * H + y) * W;
    float m = -1e30f;
#pragma unroll
    for (int k = 0; k < 7; k++) {
        int x = ox - 1 + k;
        if (x >= 0 && x < W) m = fmaxf(m, row[x]);
    }
    out[idx] = m;
}

__global__ void poolV_kernel(const float* __restrict__ in, float* __restrict__ out,
                             int planes, int H, int W) {
    int Ho = H - 4;
    long total = (long)planes * Ho * W;
    long idx = (long)blockIdx.x * 256 + threadIdx.x;
    if (idx >= total) return;
    int x = (int)(idx % W);
    long rest = idx / W;
    int oy = (int)(rest % Ho);
    long pl = rest / Ho;
    const float* base = in + (long)pl * H * W;
    float m = -1e30f;
#pragma unroll
    for (int k = 0; k < 7; k++) {
        int r = oy - 1 + k;
        if (r >= 0 && r < H) m = fmaxf(m, base[(long)r * W + x]);
    }
    out[idx] = m;
}

// ---------------- generic fp32 GEMM (+epilogue) ----------------
__device__ __forceinline__ float gelu_exact(float v) {
    return 0.5f * v * (1.0f + erff(v * 0.70710678118654752440f));
}

__global__ void gemm_kernel(const float* __restrict__ A, const float* __restrict__ W,
                            const float* __restrict__ bias, const float* resid,
                            float* C, int M, int N, int K, int mode) {
    __shared__ __align__(16) float As[16][65];
    __shared__ __align__(16) float Ws[16][64];
    int tid = threadIdx.x;
    int tx = tid & 15, ty = tid >> 4;
    int n0 = blockIdx.x * 64, m0 = blockIdx.y * 64;
    int kpb = K / gridDim.z;
    int kbeg = blockIdx.z * kpb, kend = kbeg + kpb;

    float acc[4][4];
#pragma unroll
    for (int i = 0; i < 4; i++)
#pragma unroll
        for (int j = 0; j < 4; j++) acc[i][j] = 0.f;

    int a_m = tid >> 2, a_k4 = (tid & 3) * 4;
    int w_k = tid >> 4, w_n4 = (tid & 15) * 4;

    for (int k0 = kbeg; k0 < kend; k0 += 16) {
        float4 av = make_float4(0.f, 0.f, 0.f, 0.f);
        if (m0 + a_m < M)
            av = *(const float4*)(A + (size_t)(m0 + a_m) * K + k0 + a_k4);
        As[a_k4 + 0][a_m] = av.x;
        As[a_k4 + 1][a_m] = av.y;
        As[a_k4 + 2][a_m] = av.z;
        As[a_k4 + 3][a_m] = av.w;
        *(float4*)&Ws[w_k][w_n4] = *(const float4*)(W + (size_t)(k0 + w_k) * N + n0 + w_n4);
        __syncthreads();
#pragma unroll
        for (int kk = 0; kk < 16; kk++) {
            float4 bv = *(const float4*)&Ws[kk][tx * 4];
            float a0 = As[kk][ty * 4 + 0];
            float a1 = As[kk][ty * 4 + 1];
            float a2 = As[kk][ty * 4 + 2];
            float a3 = As[kk][ty * 4 + 3];
            acc[0][0] += a0 * bv.x; acc[0][1] += a0 * bv.y; acc[0][2] += a0 * bv.z; acc[0][3] += a0 * bv.w;
            acc[1][0] += a1 * bv.x; acc[1][1] += a1 * bv.y; acc[1][2] += a1 * bv.z; acc[1][3] += a1 * bv.w;
            acc[2][0] += a2 * bv.x; acc[2][1] += a2 * bv.y; acc[2][2] += a2 * bv.z; acc[2][3] += a2 * bv.w;
            acc[3][0] += a3 * bv.x; acc[3][1] += a3 * bv.y; acc[3][2] += a3 * bv.z; acc[3][3] += a3 * bv.w;
        }
        __syncthreads();
    }

#pragma unroll
    for (int i = 0; i < 4; i++) {
        int m = m0 + ty * 4 + i;
        if (m >= M) continue;
#pragma unroll
        for (int j = 0; j < 4; j++) {
            int n = n0 + tx * 4 + j;
            float v = acc[i][j];
            if (mode == 3) {
                atomicAdd(&C[(size_t)m * N + n], v);
            } else {
                if (bias) v += bias[n];
                if (mode == 2) v = gelu_exact(v);
                if (mode == 1) v += resid[(size_t)m * N + n];
                C[(size_t)m * N + n] = v;
            }
        }
    }
}

// ---------------- layernorm (width 512) ----------------
__global__ void ln_kernel(const float* __restrict__ in, int row_stride,
                          const float* __restrict__ g, const float* __restrict__ b,
                          float* __restrict__ out) {
    int r = blockIdx.x;
    const float* x = in + (size_t)r * row_stride;
    int tid = threadIdx.x;  // 128
    float4 v = *(const float4*)(x + tid * 4);
    float s = v.x + v.y + v.z + v.w;
    float ss = v.x * v.x + v.y * v.y + v.z * v.z + v.w * v.w;
    __shared__ float rs[4], rss[4];
#pragma unroll
    for (int o = 16; o > 0; o >>= 1) {
        s += __shfl_down_sync(0xffffffffu, s, o);
        ss += __shfl_down_sync(0xffffffffu, ss, o);
    }
    int lane = tid & 31, wp = tid >> 5;
    if (lane == 0) { rs[wp] = s; rss[wp] = ss; }
    __syncthreads();
    float S = rs[0] + rs[1] + rs[2] + rs[3];
    float SS = rss[0] + rss[1] + rss[2] + rss[3];
    float mean = S * (1.f / 512.f);
    float var = SS * (1.f / 512.f) - mean * mean;
    float inv = rsqrtf(var + 1e-5f);
    float4 gv = *(const float4*)(g + tid * 4);
    float4 bv = *(const float4*)(b + tid * 4);
    float4 o;
    o.x = (v.x - mean) * inv * gv.x + bv.x;
    o.y = (v.y - mean) * inv * gv.y + bv.y;
    o.z = (v.z - mean) * inv * gv.z + bv.z;
    o.w = (v.w - mean) * inv * gv.w + bv.w;
    *(float4*)(out + (size_t)r * 512 + tid * 4) = o;
}

// ---------------- attention: per (head, batch) block ----------------
__global__ void attn_kernel(const float* __restrict__ qkv, float* __restrict__ attnout) {
    int h = blockIdx.x, b = blockIdx.y;
    __shared__ float sq[17][65], sk[17][65], sv[17][65], sp[17][18];
    int tid = threadIdx.x;  // 128
    for (int idx = tid; idx < 17 * 64; idx += 128) {
        int n = idx >> 6, d = idx & 63;
        const float* row = qkv + (size_t)(b * 17 + n) * 1536 + h * 64 + d;
        sq[n][d] = row[0];
        sk[n][d] = row[512];
        sv[n][d] = row[1024];
    }
    __syncthreads();
    for (int idx = tid; idx < 289; idx += 128) {
        int qi = idx / 17, ki = idx % 17;
        float s = 0.f;
#pragma unroll
        for (int d = 0; d < 64; d++) s += sq[qi][d] * sk[ki][d];
        sp[qi][ki] = s * 0.125f;
    }
    __syncthreads();
    if (tid < 17) {
        float m = -1e30f;
        for (int k = 0; k < 17; k++) m = fmaxf(m, sp[tid][k]);
        float sum = 0.f;
        for (int k = 0; k < 17; k++) { float e = expf(sp[tid][k] - m); sp[tid][k] = e; sum += e; }
        float inv = 1.f / sum;
        for (int k = 0; k < 17; k++) sp[tid][k] *= inv;
    }
    __syncthreads();
    for (int idx = tid; idx < 17 * 64; idx += 128) {
        int n = idx >> 6, d = idx & 63;
        float o = 0.f;
#pragma unroll
        for (int k = 0; k < 17; k++) o += sp[n][k] * sv[k][d];
        attnout[(size_t)(b * 17 + n) * 512 + h * 64 + d] = o;
    }
}

// ---------------- assemble tokens ----------------
__global__ void assemble_kernel(const float* __restrict__ xproj, const float* __restrict__ flat_b,
                                const float* __restrict__ cls_token, const float* __restrict__ pos_emb,
                                float* __restrict__ x) {
    int idx = blockIdx.x * 256 + threadIdx.x;
    if (idx >= BATCH * NTOK * DIM) return;
    int d = idx & 511;
    int r = (idx >> 9) % NTOK;
    int b = idx / (NTOK * DIM);
    float v;
    if (r == 0)
        v = cls_token[d] + pos_emb[d];
    else
        v = xproj[(size_t)(b * NPATCH + (r - 1)) * DIM + d] + flat_b[d] + pos_emb[r * DIM + d];
    x[idx] = v;
}

__global__ void zero_kernel(float* p, int n) {
    int i = blockIdx.x * 256 + threadIdx.x;
    if (i < n) p[i] = 0.f;
}

// ---------------- head ----------------
__global__ void head_kernel(const float* __restrict__ cls, const float* __restrict__ hw,
                            const float* __restrict__ hb, float* __restrict__ out) {
    int b = blockIdx.x;
    __shared__ float s[512];
    int tid = threadIdx.x;  // 256
    s[tid] = cls[(size_t)b * 512 + tid];
    s[tid + 256] = cls[(size_t)b * 512 + tid + 256];
    __syncthreads();
    for (int c = tid; c < NC; c += 256) {
        float acc = hb[c];
        for (int k = 0; k < 512; k++) acc += s[k] * hw[(size_t)k * NC + c];
        out[(size_t)b * NC + c] = acc;
    }
}

// ---------------- launch ----------------
static inline int cdiv_l(long a, int b) { return (int)((a + b - 1) / b); }

extern "C" void kernel_launch(void* const* d_in, const int* in_sizes, int n_in,
                              void* d_out, int out_size) {
    const float* img      = (const float*)d_in[0];
    const float* conv1_w  = (const float*)d_in[1];
    const float* conv2_w  = (const float*)d_in[2];
    const float* conv3_w  = (const float*)d_in[3];
    const float* flat_w   = (const float*)d_in[4];
    const float* flat_b   = (const float*)d_in[5];
    const float* cls_tok  = (const float*)d_in[6];
    const float* pos_emb  = (const float*)d_in[7];
    const float* ln1_g    = (const float*)d_in[8];
    const float* ln1_b    = (const float*)d_in[9];
    const float* qkv_w    = (const float*)d_in[10];
    const float* out_w    = (const float*)d_in[11];
    const float* out_b    = (const float*)d_in[12];
    const float* ln2_g    = (const float*)d_in[13];
    const float* ln2_b    = (const float*)d_in[14];
    const float* ff1_w    = (const float*)d_in[15];
    const float* ff1_b    = (const float*)d_in[16];
    const float* ff2_w    = (const float*)d_in[17];
    const float* ff2_b    = (const float*)d_in[18];
    const float* hln_g    = (const float*)d_in[19];
    const float* hln_b    = (const float*)d_in[20];
    const float* head_w   = (const float*)d_in[21];
    const float* head_b   = (const float*)d_in[22];
    float* outp = (float*)d_out;

    float *A, *Bb, *xproj, *x, *h, *qkv, *attn, *ff, *cls;
    cudaGetSymbolAddress((void**)&A, g_A);
    cudaGetSymbolAddress((void**)&Bb, g_B);
    cudaGetSymbolAddress((void**)&xproj, g_xproj);
    cudaGetSymbolAddress((void**)&x, g_x);
    cudaGetSymbolAddress((void**)&h, g_h);
    cudaGetSymbolAddress((void**)&qkv, g_qkv);
    cudaGetSymbolAddress((void**)&attn, g_attn);
    cudaGetSymbolAddress((void**)&ff, g_ff);
    cudaGetSymbolAddress((void**)&cls, g_cls);

    // --- CNN stage 1 ---
    conv1_kernel<<<dim3(7, 8, PB), 256>>>(img, conv1_w, A);
    {
        long t = (long)PB * 32 * 107 * 103;
        poolH_kernel<<<cdiv_l(t, 256), 256>>>(A, Bb, PB * 32, 107, 107);
        t = (long)PB * 32 * 103 * 103;
        poolV_kernel<<<cdiv_l(t, 256), 256>>>(Bb, A, PB * 32, 107, 103);
    }
    // --- CNN stage 2 ---
    conv2_kernel<<<dim3(2, 8, PB), 352>>>(A, conv2_w, Bb);
    {
        long t = (long)PB * 64 * 49 * 45;
        poolH_kernel<<<cdiv_l(t, 256), 256>>>(Bb, A, PB * 64, 49, 49);
        t = (long)PB * 64 * 45 * 45;
        poolV_kernel<<<cdiv_l(t, 256), 256>>>(A, Bb, PB * 64, 49, 45);
    }
    // --- CNN stage 3 ---
    conv3_kernel<<<dim3(4, PB), 400>>>(Bb, conv3_w, A);
    {
        long t = (long)PB * 64 * 20 * 16;
        poolH_kernel<<<cdiv_l(t, 256), 256>>>(A, Bb, PB * 64, 20, 20);
        t = (long)PB * 64 * 16 * 16;
        poolV_kernel<<<cdiv_l(t, 256), 256>>>(Bb, A, PB * 64, 20, 16);
    }
    // feat = A : [256, 16384]

    // --- flat projection (split-K=8, atomic) ---
    zero_kernel<<<cdiv_l(PB * DIM, 256), 256>>>(xproj, PB * DIM);
    gemm_kernel<<<dim3(DIM / 64, PB / 64, 8), 256>>>(A, flat_w, nullptr, nullptr, xproj,
                                                     PB, DIM, 16384, 3);
    assemble_kernel<<<cdiv_l(BATCH * NTOK * DIM, 256), 256>>>(xproj, flat_b, cls_tok, pos_emb, x);

    // --- transformer ---
    for (int l = 0; l < DEPTH; l++) {
        const float* qw = qkv_w + (size_t)l * DIM * 3 * DIM;
        const float* ow = out_w + (size_t)l * DIM * DIM;
        const float* ob = out_b + (size_t)l * DIM;
        const float* w1 = ff1_w + (size_t)l * DIM * MLP_;
        const float* b1 = ff1_b + (size_t)l * MLP_;
        const float* w2 = ff2_w + (size_t)l * MLP_ * DIM;
        const float* b2 = ff2_b + (size_t)l * DIM;

        ln_kernel<<<ROWS, 128>>>(x, DIM, ln1_g + l * DIM, ln1_b + l * DIM, h);
        gemm_kernel<<<dim3(1536 / 64, 5, 1), 256>>>(h, qw, nullptr, nullptr, qkv,
                                                    ROWS, 1536, DIM, 0);
        attn_kernel<<<dim3(HEADS, BATCH), 128>>>(qkv, attn);
        gemm_kernel<<<dim3(DIM / 64, 5, 1), 256>>>(attn, ow, ob, x, x,
                                                   ROWS, DIM, DIM, 1);
        ln_kernel<<<ROWS, 128>>>(x, DIM, ln2_g + l * DIM, ln2_b + l * DIM, h);
        gemm_kernel<<<dim3(MLP_ / 64, 5, 1), 256>>>(h, w1, b1, nullptr, ff,
                                                    ROWS, MLP_, DIM, 2);
        gemm_kernel<<<dim3(DIM / 64, 5, 1), 256>>>(ff, w2, b2, x, x,
                                                   ROWS, DIM, MLP_, 1);
    }

    // --- head ---
    ln_kernel<<<BATCH, 128>>>(x, NTOK * DIM, hln_g, hln_b, cls);
    head_kernel<<<BATCH, 256>>>(cls, head_w, head_b, outp);
}

// round 14
// speedup vs baseline: 1.3104x; 1.0432x over previous
#include <cuda_runtime.h>
#include <cuda_bf16.h>
#include <math.h>

// ---------------- constants ----------------
#define BATCH 16
#define NPATCH 16
#define PB 256            // BATCH * NPATCH
#define PSIZE 220
#define DIM 512
#define DEPTH 6
#define HEADS 8
#define DH 64
#define MLP_ 2048
#define NC 1000
#define NTOK 17
#define ROWS 272          // BATCH * NTOK

// CNN stage dims: conv1 220->107, pool->103; conv2 103->49, pool->45; conv3 45->20, pool->16

// ---------------- scratch (device globals; no allocation) ----------------
__device__ __align__(16) float g_A[93763584];
__device__ __align__(16) float g_B[90259456];
__device__ __align__(16) float g_xproj[PB * DIM];
__device__ __align__(16) float g_x[ROWS * DIM];
__device__ __align__(16) float g_h[ROWS * DIM];
__device__ __align__(16) float g_qkv[ROWS * 3 * DIM];
__device__ __align__(16) float g_attn[ROWS * DIM];
__device__ __align__(16) float g_ff[ROWS * MLP_];
__device__ __align__(16) float g_cls[BATCH * DIM];

// ---------------- packed fp32x2 helpers (bit-exact vs scalar FFMA) ----------------
typedef unsigned long long u64_t;
__device__ __forceinline__ u64_t pack2b(float v) {
    u64_t r;
    asm("mov.b64 %0, {%1, %1};" : "=l"(r) : "f"(v));
    return r;
}
__device__ __forceinline__ void ffma2(u64_t& d, u64_t a, u64_t b) {
    asm("fma.rn.f32x2 %0, %1, %2, %0;" : "+l"(d) : "l"(a), "l"(b));
}
__device__ __forceinline__ float2 unpack2(u64_t v) {
    float2 o;
    asm("mov.b64 {%0, %1}, %2;" : "=f"(o.x), "=f"(o.y) : "l"(v));
    return o;
}

// ---------------- conv1: img patches -> [256,32,107,107], ReLU fused ----------------
// grid (7 xtiles, 4 ytiles * 2 ocg, 256 patches), block 256 = (ly 0..15, lx 0..15)
__global__ __launch_bounds__(256, 3) void conv1_kernel(const float* __restrict__ img,
                                                       const float* __restrict__ w,
                                                       float* __restrict__ out) {
    __shared__ __align__(16) float s_in[69 * 38];   // de-interleaved: even cols [0..18], odd [19..36]
    __shared__ __align__(16) float s_w[49 * 16];    // [tap][oc_local]
    int p = blockIdx.z;
    int b = p >> 4, gh = (p >> 2) & 3, gw = p & 3;
    int ytile = blockIdx.y & 3, ocg = blockIdx.y >> 2;
    int tx0 = blockIdx.x * 16, ty0 = ytile * 32;
    int tid = threadIdx.x;
    int ly = tid >> 4, lx = tid & 15;

    for (int i = tid; i < 49 * 16; i += 256) {
        int ol = i & 15, tap = i >> 4;
        s_w[i] = w[(ocg * 16 + ol) * 49 + tap];
    }
    const float* ibase = img + (size_t)b * 880 * 880 + (size_t)(gh * PSIZE) * 880 + gw * PSIZE;
    int iy0 = ty0 * 2, ix0 = tx0 * 2;
    for (int i = tid; i < 69 * 37; i += 256) {
        int r = i / 37, c = i % 37;
        int y = iy0 + r, x = ix0 + c;
        float v = (y < PSIZE && x < PSIZE) ? ibase[(size_t)y * 880 + x] : 0.f;
        s_in[r * 38 + ((c & 1) ? 19 : 0) + (c >> 1)] = v;
    }
    __syncthreads();

    u64_t acc[2][8];
#pragma unroll
    for (int r = 0; r < 2; r++)
#pragma unroll
        for (int j = 0; j < 8; j++) acc[r][j] = 0ull;

#pragma unroll 1
    for (int dy = 0; dy < 7; dy++) {
#pragma unroll
        for (int dx = 0; dx < 7; dx++) {
            const ulonglong2* w2 = (const ulonglong2*)&s_w[(dy * 7 + dx) * 16];
            ulonglong2 ta = w2[0], tb = w2[1], tc = w2[2], td = w2[3];
            int cb = ((dx & 1) ? 19 : 0) + lx + (dx >> 1);
#pragma unroll
            for (int r = 0; r < 2; r++) {
                float iv = s_in[(4 * ly + 2 * r + dy) * 38 + cb];
                u64_t ivp = pack2b(iv);
                ffma2(acc[r][0], ivp, ta.x); ffma2(acc[r][1], ivp, ta.y);
                ffma2(acc[r][2], ivp, tb.x); ffma2(acc[r][3], ivp, tb.y);
                ffma2(acc[r][4], ivp, tc.x); ffma2(acc[r][5], ivp, tc.y);
                ffma2(acc[r][6], ivp, td.x); ffma2(acc[r][7], ivp, td.y);
            }
        }
    }

#pragma unroll
    for (int r = 0; r < 2; r++) {
        int oy = ty0 + 2 * ly + r, ox = tx0 + lx;
        if (oy < 107 && ox < 107) {
            size_t obase = ((size_t)p * 32 + ocg * 16) * 11449 + (size_t)oy * 107 + ox;
#pragma unroll
            for (int j = 0; j < 8; j++) {
                float2 v = unpack2(acc[r][j]);
                out[obase + (size_t)(2 * j) * 11449]     = fmaxf(v.x, 0.f);
                out[obase + (size_t)(2 * j + 1) * 11449] = fmaxf(v.y, 0.f);
            }
        }
    }
}

// ---------------- conv2: [256,32,103,103] -> [256,64,49,49], ReLU fused ----------------
// grid (4 ytiles, 8 ocg of 8, 256 patches), block 352 (343 active = ly 0..6 x lx 0..48)
// thread: 2 out rows {14*ytile+2ly+k}, 1 col, 8 oc -> acc[2][4] u64 (32 regs) -> 4 blocks/SM
__global__ __launch_bounds__(352, 4) void conv2_kernel(const float* __restrict__ in,
                                                       const float* __restrict__ w,
                                                       float* __restrict__ out) {
    __shared__ __align__(16) float s_in[33 * 104];  // de-interleaved: even [0..51], odd [52..102]
    __shared__ __align__(16) float s_w[49 * 8];     // [tap][oc_local]
    int ytile = blockIdx.x, g = blockIdx.y, p = blockIdx.z;
    int tid = threadIdx.x;
    int ly = tid / 49, lx = tid % 49;
    bool active = tid < 343;

    u64_t acc[2][4];
#pragma unroll
    for (int k = 0; k < 2; k++)
#pragma unroll
        for (int j = 0; j < 4; j++) acc[k][j] = 0ull;

    const float* inp = in + (size_t)p * 32 * 103 * 103;
    const float* wp = w + (size_t)g * 8 * 32 * 49;
    int rbase = 28 * ytile;

    for (int ic = 0; ic < 32; ic++) {
        __syncthreads();
        const float* plane = inp + (size_t)ic * 103 * 103;
        for (int i = tid; i < 33 * 103; i += 352) {
            int r = i / 103, c = i % 103;
            int gr = rbase + r; if (gr > 102) gr = 102;
            s_in[r * 104 + ((c & 1) ? 52 : 0) + (c >> 1)] = plane[gr * 103 + c];
        }
        for (int i = tid; i < 49 * 8; i += 352) {
            int tap = i >> 3, ol = i & 7;
            s_w[i] = wp[(size_t)(ol * 32 + ic) * 49 + tap];
        }
        __syncthreads();
        if (!active) continue;
#pragma unroll 1
        for (int dy = 0; dy < 7; dy++) {
#pragma unroll
            for (int dx = 0; dx < 7; dx++) {
                const ulonglong2* w2 = (const ulonglong2*)&s_w[(dy * 7 + dx) * 8];
                ulonglong2 t0 = w2[0], t1 = w2[1];
                int cb = ((dx & 1) ? 52 : 0) + lx + (dx >> 1);
#pragma unroll
                for (int k = 0; k < 2; k++) {
                    float iv = s_in[(4 * ly + 2 * k + dy) * 104 + cb];
                    u64_t ivp = pack2b(iv);
                    ffma2(acc[k][0], ivp, t0.x); ffma2(acc[k][1], ivp, t0.y);
                    ffma2(acc[k][2], ivp, t1.x); ffma2(acc[k][3], ivp, t1.y);
                }
            }
        }
    }
    if (active) {
#pragma unroll
        for (int k = 0; k < 2; k++) {
            int oy = ytile * 14 + 2 * ly + k;
            if (oy < 49) {
                size_t obase = ((size_t)p * 64 + g * 8) * 2401 + (size_t)oy * 49 + lx;
#pragma unroll
                for (int j = 0; j < 4; j++) {
                    float2 v = unpack2(acc[k][j]);
                    out[obase + (size_t)(2 * j) * 2401]     = fmaxf(v.x, 0.f);
                    out[obase + (size_t)(2 * j + 1) * 2401] = fmaxf(v.y, 0.f);
                }
            }
        }
    }
}

// ---------------- conv3: [256,64,45,45] -> [256,64,20,20], ReLU fused ----------------
// grid (2 ytiles * 2 ocg of 32, 256 patches), block 400 = (sub 0..3 of 8 oc, ry 0..4, lx 0..19)
__global__ __launch_bounds__(400, 3) void conv3_kernel(const float* __restrict__ in,
                                                       const float* __restrict__ w,
                                                       float* __restrict__ out) {
    __shared__ __align__(16) float s_in[45 * 46];   // de-interleaved: even [0..22], odd [23..44]
    __shared__ __align__(16) float s_w[49 * 32];    // [tap][oc_local]
    int ytile = blockIdx.x & 1, ocg = blockIdx.x >> 1;
    int p = blockIdx.y;
    int tid = threadIdx.x;
    int sub = tid / 100, r100 = tid % 100;
    int ry = r100 / 20, lx = r100 % 20;

    u64_t acc[2][4];
#pragma unroll
    for (int k = 0; k < 2; k++)
#pragma unroll
        for (int j = 0; j < 4; j++) acc[k][j] = 0ull;

    const float* inp = in + (size_t)p * 64 * 45 * 45;

    for (int ic = 0; ic < 64; ic++) {
        __syncthreads();
        const float* plane = inp + (size_t)ic * 45 * 45;
        for (int i = tid; i < 45 * 45; i += 400) {
            int r = i / 45, c = i % 45;
            s_in[r * 46 + ((c & 1) ? 23 : 0) + (c >> 1)] = plane[i];
        }
        for (int i = tid; i < 49 * 32; i += 400) {
            int tap = i >> 5, ol = i & 31;
            s_w[i] = w[(size_t)((ocg * 32 + ol) * 64 + ic) * 49 + tap];
        }
        __syncthreads();
#pragma unroll 1
        for (int dy = 0; dy < 7; dy++) {
#pragma unroll
            for (int dx = 0; dx < 7; dx++) {
                const ulonglong2* w2 = (const ulonglong2*)&s_w[(dy * 7 + dx) * 32 + sub * 8];
                ulonglong2 t0 = w2[0], t1 = w2[1];
                int cb = ((dx & 1) ? 23 : 0) + lx + (dx >> 1);
#pragma unroll
                for (int k = 0; k < 2; k++) {
                    float iv = s_in[(20 * ytile + 4 * ry + 2 * k + dy) * 46 + cb];
                    u64_t ivp = pack2b(iv);
                    ffma2(acc[k][0], ivp, t0.x); ffma2(acc[k][1], ivp, t0.y);
                    ffma2(acc[k][2], ivp, t1.x); ffma2(acc[k][3], ivp, t1.y);
                }
            }
        }
    }
#pragma unroll
    for (int k = 0; k < 2; k++) {
        int oy = ytile * 10 + 2 * ry + k;
        size_t obase = ((size_t)p * 64 + ocg * 32 + sub * 8) * 400 + (size_t)oy * 20 + lx;
#pragma unroll
        for (int j = 0; j < 4; j++) {
            float2 v = unpack2(acc[k][j]);
            out[obase + (size_t)(2 * j) * 400]     = fmaxf(v.x, 0.f);
            out[obase + (size_t)(2 * j + 1) * 400] = fmaxf(v.y, 0.f);
        }
    }
}

// ---------------- fused maxpool 7x7 s1 p1 (single pass, smem separable) ----------------
// grid (tilesX, tilesY, planes), block 256. out tile 32x32 per block.
__global__ __launch_bounds__(256) void pool_kernel(const float* __restrict__ in,
                                                   float* __restrict__ out,
                                                   int H, int W) {
    int Ho = H - 4, Wo = W - 4;
    __shared__ float s_in[38 * 40];
    __shared__ float s_h[38 * 36];
    int pl = blockIdx.z;
    const float* ip = in + (size_t)pl * H * W;
    float* op = out + (size_t)pl * Ho * Wo;
    int ox0 = blockIdx.x * 32, oy0 = blockIdx.y * 32;
    int tid = threadIdx.x;

    // load 38x38 input region (rows oy0-1..oy0+36, cols ox0-1..ox0+36), -inf pad
    for (int i = tid; i < 38 * 38; i += 256) {
        int r = i / 38, c = i % 38;
        int y = oy0 - 1 + r, x = ox0 - 1 + c;
        float v = (y >= 0 && y < H && x >= 0 && x < W) ? ip[(size_t)y * W + x] : -1e30f;
        s_in[r * 40 + c] = v;
    }
    __syncthreads();

    // H pass: 38 rows x 32 cols, 4-col chunks per thread
    for (int u = tid; u < 38 * 8; u += 256) {
        int r = u >> 3, c4 = (u & 7) * 4;
        float v[10];
#pragma unroll
        for (int j = 0; j < 10; j++) v[j] = s_in[r * 40 + c4 + j];
        float m_com = fmaxf(fmaxf(v[3], v[4]), fmaxf(v[5], v[6]));
        s_h[r * 36 + c4 + 0] = fmaxf(m_com, fmaxf(v[0], fmaxf(v[1], v[2])));
        s_h[r * 36 + c4 + 1] = fmaxf(m_com, fmaxf(v[1], fmaxf(v[2], v[7])));
        s_h[r * 36 + c4 + 2] = fmaxf(m_com, fmaxf(v[2], fmaxf(v[7], v[8])));
        s_h[r * 36 + c4 + 3] = fmaxf(m_com, fmaxf(v[7], fmaxf(v[8], v[9])));
    }
    __syncthreads();

    // V pass: 32 out rows x 32 cols, 4-row chunks per thread
    for (int u = tid; u < 8 * 32; u += 256) {
        int r4 = (u >> 5) * 4, c = u & 31;
        float v[10];
#pragma unroll
        for (int j = 0; j < 10; j++) v[j] = s_h[(r4 + j) * 36 + c];
        float m_com = fmaxf(fmaxf(v[3], v[4]), fmaxf(v[5], v[6]));
        float o0 = fmaxf(m_com, fmaxf(v[0], fmaxf(v[1], v[2])));
        float o1 = fmaxf(m_com, fmaxf(v[1], fmaxf(v[2], v[7])));
        float o2 = fmaxf(m_com, fmaxf(v[2], fmaxf(v[7], v[8])));
        float o3 = fmaxf(m_com, fmaxf(v[7], fmaxf(v[8], v[9])));
        int ox = ox0 + c;
        if (ox < Wo) {
            int oy = oy0 + r4;
            if (oy + 0 < Ho) op[(size_t)(oy + 0) * Wo + ox] = o0;
            if (oy + 1 < Ho) op[(size_t)(oy + 1) * Wo + ox] = o1;
            if (oy + 2 < Ho) op[(size_t)(oy + 2) * Wo + ox] = o2;
            if (oy + 3 < Ho) op[(size_t)(oy + 3) * Wo + ox] = o3;
        }
    }
}

// ---------------- generic fp32 GEMM (+epilogue) ----------------
__device__ __forceinline__ float gelu_exact(float v) {
    return 0.5f * v * (1.0f + erff(v * 0.70710678118654752440f));
}

__global__ void gemm_kernel(const float* __restrict__ A, const float* __restrict__ W,
                            const float* __restrict__ bias, const float* resid,
                            float* C, int M, int N, int K, int mode) {
    __shared__ __align__(16) float As[16][65];
    __shared__ __align__(16) float Ws[16][64];
    int tid = threadIdx.x;
    int tx = tid & 15, ty = tid >> 4;
    int n0 = blockIdx.x * 64, m0 = blockIdx.y * 64;
    int kpb = K / gridDim.z;
    int kbeg = blockIdx.z * kpb, kend = kbeg + kpb;

    float acc[4][4];
#pragma unroll
    for (int i = 0; i < 4; i++)
#pragma unroll
        for (int j = 0; j < 4; j++) acc[i][j] = 0.f;

    int a_m = tid >> 2, a_k4 = (tid & 3) * 4;
    int w_k = tid >> 4, w_n4 = (tid & 15) * 4;

    for (int k0 = kbeg; k0 < kend; k0 += 16) {
        float4 av = make_float4(0.f, 0.f, 0.f, 0.f);
        if (m0 + a_m < M)
            av = *(const float4*)(A + (size_t)(m0 + a_m) * K + k0 + a_k4);
        As[a_k4 + 0][a_m] = av.x;
        As[a_k4 + 1][a_m] = av.y;
        As[a_k4 + 2][a_m] = av.z;
        As[a_k4 + 3][a_m] = av.w;
        *(float4*)&Ws[w_k][w_n4] = *(const float4*)(W + (size_t)(k0 + w_k) * N + n0 + w_n4);
        __syncthreads();
#pragma unroll
        for (int kk = 0; kk < 16; kk++) {
            float4 bv = *(const float4*)&Ws[kk][tx * 4];
            float a0 = As[kk][ty * 4 + 0];
            float a1 = As[kk][ty * 4 + 1];
            float a2 = As[kk][ty * 4 + 2];
            float a3 = As[kk][ty * 4 + 3];
            acc[0][0] += a0 * bv.x; acc[0][1] += a0 * bv.y; acc[0][2] += a0 * bv.z; acc[0][3] += a0 * bv.w;
            acc[1][0] += a1 * bv.x; acc[1][1] += a1 * bv.y; acc[1][2] += a1 * bv.z; acc[1][3] += a1 * bv.w;
            acc[2][0] += a2 * bv.x; acc[2][1] += a2 * bv.y; acc[2][2] += a2 * bv.z; acc[2][3] += a2 * bv.w;
            acc[3][0] += a3 * bv.x; acc[3][1] += a3 * bv.y; acc[3][2] += a3 * bv.z; acc[3][3] += a3 * bv.w;
        }
        __syncthreads();
    }

#pragma unroll
    for (int i = 0; i < 4; i++) {
        int m = m0 + ty * 4 + i;
        if (m >= M) continue;
#pragma unroll
        for (int j = 0; j < 4; j++) {
            int n = n0 + tx * 4 + j;
            float v = acc[i][j];
            if (mode == 3) {
                atomicAdd(&C[(size_t)m * N + n], v);
            } else {
                if (bias) v += bias[n];
                if (mode == 2) v = gelu_exact(v);
                if (mode == 1) v += resid[(size_t)m * N + n];
                C[(size_t)m * N + n] = v;
            }
        }
    }
}

// ---------------- layernorm (width 512) ----------------
__global__ void ln_kernel(const float* __restrict__ in, int row_stride,
                          const float* __restrict__ g, const float* __restrict__ b,
                          float* __restrict__ out) {
    int r = blockIdx.x;
    const float* x = in + (size_t)r * row_stride;
    int tid = threadIdx.x;  // 128
    float4 v = *(const float4*)(x + tid * 4);
    float s = v.x + v.y + v.z + v.w;
    float ss = v.x * v.x + v.y * v.y + v.z * v.z + v.w * v.w;
    __shared__ float rs[4], rss[4];
#pragma unroll
    for (int o = 16; o > 0; o >>= 1) {
        s += __shfl_down_sync(0xffffffffu, s, o);
        ss += __shfl_down_sync(0xffffffffu, ss, o);
    }
    int lane = tid & 31, wp = tid >> 5;
    if (lane == 0) { rs[wp] = s; rss[wp] = ss; }
    __syncthreads();
    float S = rs[0] + rs[1] + rs[2] + rs[3];
    float SS = rss[0] + rss[1] + rss[2] + rss[3];
    float mean = S * (1.f / 512.f);
    float var = SS * (1.f / 512.f) - mean * mean;
    float inv = rsqrtf(var + 1e-5f);
    float4 gv = *(const float4*)(g + tid * 4);
    float4 bv = *(const float4*)(b + tid * 4);
    float4 o;
    o.x = (v.x - mean) * inv * gv.x + bv.x;
    o.y = (v.y - mean) * inv * gv.y + bv.y;
    o.z = (v.z - mean) * inv * gv.z + bv.z;
    o.w = (v.w - mean) * inv * gv.w + bv.w;
    *(float4*)(out + (size_t)r * 512 + tid * 4) = o;
}

// ---------------- attention: per (head, batch) block ----------------
__global__ void attn_kernel(const float* __restrict__ qkv, float* __restrict__ attnout) {
    int h = blockIdx.x, b = blockIdx.y;
    __shared__ float sq[17][65], sk[17][65], sv[17][65], sp[17][18];
    int tid = threadIdx.x;  // 128
    for (int idx = tid; idx < 17 * 64; idx += 128) {
        int n = idx >> 6, d = idx & 63;
        const float* row = qkv + (size_t)(b * 17 + n) * 1536 + h * 64 + d;
        sq[n][d] = row[0];
        sk[n][d] = row[512];
        sv[n][d] = row[1024];
    }
    __syncthreads();
    for (int idx = tid; idx < 289; idx += 128) {
        int qi = idx / 17, ki = idx % 17;
        float s = 0.f;
#pragma unroll
        for (int d = 0; d < 64; d++) s += sq[qi][d] * sk[ki][d];
        sp[qi][ki] = s * 0.125f;
    }
    __syncthreads();
    if (tid < 17) {
        float m = -1e30f;
        for (int k = 0; k < 17; k++) m = fmaxf(m, sp[tid][k]);
        float sum = 0.f;
        for (int k = 0; k < 17; k++) { float e = expf(sp[tid][k] - m); sp[tid][k] = e; sum += e; }
        float inv = 1.f / sum;
        for (int k = 0; k < 17; k++) sp[tid][k] *= inv;
    }
    __syncthreads();
    for (int idx = tid; idx < 17 * 64; idx += 128) {
        int n = idx >> 6, d = idx & 63;
        float o = 0.f;
#pragma unroll
        for (int k = 0; k < 17; k++) o += sp[n][k] * sv[k][d];
        attnout[(size_t)(b * 17 + n) * 512 + h * 64 + d] = o;
    }
}

// ---------------- assemble tokens ----------------
__global__ void assemble_kernel(const float* __restrict__ xproj, const float* __restrict__ flat_b,
                                const float* __restrict__ cls_token, const float* __restrict__ pos_emb,
                                float* __restrict__ x) {
    int idx = blockIdx.x * 256 + threadIdx.x;
    if (idx >= BATCH * NTOK * DIM) return;
    int d = idx & 511;
    int r = (idx >> 9) % NTOK;
    int b = idx / (NTOK * DIM);
    float v;
    if (r == 0)
        v = cls_token[d] + pos_emb[d];
    else
        v = xproj[(size_t)(b * NPATCH + (r - 1)) * DIM + d] + flat_b[d] + pos_emb[r * DIM + d];
    x[idx] = v;
}

__global__ void zero_kernel(float* p, int n) {
    int i = blockIdx.x * 256 + threadIdx.x;
    if (i < n) p[i] = 0.f;
}

// ---------------- head ----------------
__global__ void head_kernel(const float* __restrict__ cls, const float* __restrict__ hw,
                            const float* __restrict__ hb, float* __restrict__ out) {
    int b = blockIdx.x;
    __shared__ float s[512];
    int tid = threadIdx.x;  // 256
    s[tid] = cls[(size_t)b * 512 + tid];
    s[tid + 256] = cls[(size_t)b * 512 + tid + 256];
    __syncthreads();
    for (int c = tid; c < NC; c += 256) {
        float acc = hb[c];
        for (int k = 0; k < 512; k++) acc += s[k] * hw[(size_t)k * NC + c];
        out[(size_t)b * NC + c] = acc;
    }
}

// ---------------- launch ----------------
static inline int cdiv_l(long a, int b) { return (int)((a + b - 1) / b); }

extern "C" void kernel_launch(void* const* d_in, const int* in_sizes, int n_in,
                              void* d_out, int out_size) {
    const float* img      = (const float*)d_in[0];
    const float* conv1_w  = (const float*)d_in[1];
    const float* conv2_w  = (const float*)d_in[2];
    const float* conv3_w  = (const float*)d_in[3];
    const float* flat_w   = (const float*)d_in[4];
    const float* flat_b   = (const float*)d_in[5];
    const float* cls_tok  = (const float*)d_in[6];
    const float* pos_emb  = (const float*)d_in[7];
    const float* ln1_g    = (const float*)d_in[8];
    const float* ln1_b    = (const float*)d_in[9];
    const float* qkv_w    = (const float*)d_in[10];
    const float* out_w    = (const float*)d_in[11];
    const float* out_b    = (const float*)d_in[12];
    const float* ln2_g    = (const float*)d_in[13];
    const float* ln2_b    = (const float*)d_in[14];
    const float* ff1_w    = (const float*)d_in[15];
    const float* ff1_b    = (const float*)d_in[16];
    const float* ff2_w    = (const float*)d_in[17];
    const float* ff2_b    = (const float*)d_in[18];
    const float* hln_g    = (const float*)d_in[19];
    const float* hln_b    = (const float*)d_in[20];
    const float* head_w   = (const float*)d_in[21];
    const float* head_b   = (const float*)d_in[22];
    float* outp = (float*)d_out;

    float *A, *Bb, *xproj, *x, *h, *qkv, *attn, *ff, *cls;
    cudaGetSymbolAddress((void**)&A, g_A);
    cudaGetSymbolAddress((void**)&Bb, g_B);
    cudaGetSymbolAddress((void**)&xproj, g_xproj);
    cudaGetSymbolAddress((void**)&x, g_x);
    cudaGetSymbolAddress((void**)&h, g_h);
    cudaGetSymbolAddress((void**)&qkv, g_qkv);
    cudaGetSymbolAddress((void**)&attn, g_attn);
    cudaGetSymbolAddress((void**)&ff, g_ff);
    cudaGetSymbolAddress((void**)&cls, g_cls);

    // --- CNN stage 1: conv1 -> A, pool A -> B ---
    conv1_kernel<<<dim3(7, 8, PB), 256>>>(img, conv1_w, A);
    pool_kernel<<<dim3(4, 4, PB * 32), 256>>>(A, Bb, 107, 107);

    // --- CNN stage 2: conv2 B -> A, pool A -> B ---
    conv2_kernel<<<dim3(4, 8, PB), 352>>>(Bb, conv2_w, A);
    pool_kernel<<<dim3(2, 2, PB * 64), 256>>>(A, Bb, 49, 49);

    // --- CNN stage 3: conv3 B -> A, pool A -> B ---
    conv3_kernel<<<dim3(4, PB), 400>>>(Bb, conv3_w, A);
    pool_kernel<<<dim3(1, 1, PB * 64), 256>>>(A, Bb, 20, 20);

    // feat = Bb : [256, 16384]

    // --- flat projection (split-K=8, atomic) ---
    zero_kernel<<<cdiv_l(PB * DIM, 256), 256>>>(xproj, PB * DIM);
    gemm_kernel<<<dim3(DIM / 64, PB / 64, 8), 256>>>(Bb, flat_w, nullptr, nullptr, xproj,
                                                     PB, DIM, 16384, 3);
    assemble_kernel<<<cdiv_l(BATCH * NTOK * DIM, 256), 256>>>(xproj, flat_b, cls_tok, pos_emb, x);

    // --- transformer ---
    for (int l = 0; l < DEPTH; l++) {
        const float* qw = qkv_w + (size_t)l * DIM * 3 * DIM;
        const float* ow = out_w + (size_t)l * DIM * DIM;
        const float* ob = out_b + (size_t)l * DIM;
        const float* w1 = ff1_w + (size_t)l * DIM * MLP_;
        const float* b1 = ff1_b + (size_t)l * MLP_;
        const float* w2 = ff2_w + (size_t)l * MLP_ * DIM;
        const float* b2 = ff2_b + (size_t)l * DIM;

        ln_kernel<<<ROWS, 128>>>(x, DIM, ln1_g + l * DIM, ln1_b + l * DIM, h);
        gemm_kernel<<<dim3(1536 / 64, 5, 1), 256>>>(h, qw, nullptr, nullptr, qkv,
                                                    ROWS, 1536, DIM, 0);
        attn_kernel<<<dim3(HEADS, BATCH), 128>>>(qkv, attn);
        gemm_kernel<<<dim3(DIM / 64, 5, 1), 256>>>(attn, ow, ob, x, x,
                                                   ROWS, DIM, DIM, 1);
        ln_kernel<<<ROWS, 128>>>(x, DIM, ln2_g + l * DIM, ln2_b + l * DIM, h);
        gemm_kernel<<<dim3(MLP_ / 64, 5, 1), 256>>>(h, w1, b1, nullptr, ff,
                                                    ROWS, MLP_, DIM, 2);
        gemm_kernel<<<dim3(DIM / 64, 5, 1), 256>>>(ff, w2, b2, x, x,
                                                   ROWS, DIM, MLP_, 1);
    }

    // --- head ---
    ln_kernel<<<BATCH, 128>>>(x, NTOK * DIM, hln_g, hln_b, cls);
    head_kernel<<<BATCH, 256>>>(cls, head_w, head_b, outp);
}